// round 6
// baseline (speedup 1.0000x reference)
#include <cuda_runtime.h>
#include <cuda_bf16.h>
#include <cstdint>

// out[b,t,s] = dot(q[b,t,:], E_h[s - t/4 + 255]),  h = b % 8
//   E_h[j] = e1[h*256 + j]        j in [0,256)
//   E_h[j] = e2[h*256 + j - 255]  j in [256,511)
// B=128, T=1024, S=256, D=64.
//
// Per block: one b, 64 t-rows, 128 s-cols. Banded GEMM M=64 x N=144 x K=192
// (3-term truncation bf16 split: D = qh*Eh + qh*El + ql*Eh; ql*El ~2^-16 dropped).
// out[t][s] = D[t][ s + 15 - t/4 ].
// Tiles use XOR-swizzled 128B rows (no padding): chunk' = chunk ^ (row & 7).

#define T_DIM 1024
#define S_DIM 256
#define D_DIM 64

constexpr int BT = 64;
constexpr int NW = 144;
constexpr int SP = 146;                      // fp32 staging stride (floats)

constexpr int SM_AH = 0;
constexpr int SM_AL = SM_AH + BT * 128;      //  8192
constexpr int SM_BH = SM_AL + BT * 128;      // 16384
constexpr int SM_BL = SM_BH + NW * 128;      // 34816
constexpr int SM_TOTAL = SM_BL + NW * 128;   // 53248
static_assert(BT * SP * 4 <= SM_TOTAL, "stage must alias inputs");

__device__ __forceinline__ uint32_t smem_u32(const void* p) {
    uint32_t a;
    asm("{ .reg .u64 t; cvta.to.shared.u64 t, %1; cvt.u32.u64 %0, t; }"
        : "=r"(a) : "l"(p));
    return a;
}

#define LDSM_X4(r0, r1, r2, r3, addr)                                        \
    asm volatile("ldmatrix.sync.aligned.m8n8.x4.shared.b16 {%0,%1,%2,%3}, [%4];" \
                 : "=r"(r0), "=r"(r1), "=r"(r2), "=r"(r3) : "r"(addr))

#define LDSM_X2(r0, r1, addr)                                                \
    asm volatile("ldmatrix.sync.aligned.m8n8.x2.shared.b16 {%0,%1}, [%2];"   \
                 : "=r"(r0), "=r"(r1) : "r"(addr))

#define MMA16816(d, a, bb)                                                   \
    asm volatile("mma.sync.aligned.m16n8k16.row.col.f32.bf16.bf16.f32 "      \
                 "{%0,%1,%2,%3}, {%4,%5,%6,%7}, {%8,%9}, {%0,%1,%2,%3};"     \
                 : "+f"((d)[0]), "+f"((d)[1]), "+f"((d)[2]), "+f"((d)[3])    \
                 : "r"((a)[0]), "r"((a)[1]), "r"((a)[2]), "r"((a)[3]),       \
                   "r"((bb)[0]), "r"((bb)[1]))

// truncation split: hi = top16 bits of each float (packed), lo = exact remainder
__device__ __forceinline__ void split2t(float a, float b, uint32_t& hi, uint32_t& lo) {
    uint32_t ua = __float_as_uint(a), ub = __float_as_uint(b);
    hi = __byte_perm(ua, ub, 0x7632);
    float ra = a - __uint_as_float(ua & 0xFFFF0000u);
    float rb = b - __uint_as_float(ub & 0xFFFF0000u);
    __nv_bfloat162 L = __floats2bfloat162_rn(ra, rb);
    lo = *reinterpret_cast<uint32_t*>(&L);
}

// swizzled byte offset of (row, 16B-chunk) within a 128B-row tile
__device__ __forceinline__ uint32_t swz(int row, int chunk) {
    return (uint32_t)(row * 128 + ((chunk ^ (row & 7)) << 4));
}

__global__ void __launch_bounds__(128, 4)
srel_mma(const float* __restrict__ q,
         const float* __restrict__ e1,
         const float* __restrict__ e2,
         float* __restrict__ out)
{
    extern __shared__ char smem[];
    const uint32_t sb = smem_u32(smem);
    const int tid  = threadIdx.x;
    const int lane = tid & 31;
    const int wid  = tid >> 5;

    const int b   = blockIdx.z;
    const int h   = b & 7;
    const int t0  = blockIdx.x * BT;
    const int sx  = blockIdx.y;
    const int sh0 = t0 >> 2;
    const int jmin = 128 * sx + 240 - sh0;   // window col c = j - jmin, c in [0,143]

    // ---- stage Q (64x64 fp32 -> bf16 hi/lo swizzled tiles) ----
    {
        const float* qb = q + ((size_t)b * T_DIM + t0) * D_DIM;
        float4 v[8];
        #pragma unroll
        for (int i = 0; i < 8; i++) {
            int idx = tid + 128 * i;
            v[i] = *reinterpret_cast<const float4*>(qb + (idx >> 4) * D_DIM + 4 * (idx & 15));
        }
        #pragma unroll
        for (int i = 0; i < 8; i++) {
            int idx = tid + 128 * i;
            int row = idx >> 4, m = idx & 15;
            uint32_t h0, l0, h1, l1;
            split2t(v[i].x, v[i].y, h0, l0);
            split2t(v[i].z, v[i].w, h1, l1);
            uint32_t off = swz(row, m >> 1) + (m & 1) * 8;
            uint32_t* pH = reinterpret_cast<uint32_t*>(smem + SM_AH + off);
            uint32_t* pL = reinterpret_cast<uint32_t*>(smem + SM_AL + off);
            pH[0] = h0; pH[1] = h1;
            pL[0] = l0; pL[1] = l1;
        }
    }
    // ---- stage E window (144 rows), two batches of 9 ----
    #pragma unroll
    for (int half = 0; half < 2; half++) {
        float4 v[9];
        #pragma unroll
        for (int i = 0; i < 9; i++) {
            int idx = tid + 128 * (9 * half + i);
            int r = idx >> 4;
            int j = jmin + r;
            if (j > 510) j = 510;   // col 143 never consumed
            const float* src = (j < 256)
                ? (e1 + (size_t)(h * 256 + j) * D_DIM)
                : (e2 + (size_t)(h * 256 + j - 255) * D_DIM);
            v[i] = *reinterpret_cast<const float4*>(src + 4 * (idx & 15));
        }
        #pragma unroll
        for (int i = 0; i < 9; i++) {
            int idx = tid + 128 * (9 * half + i);
            int r = idx >> 4, m = idx & 15;
            uint32_t h0, l0, h1, l1;
            split2t(v[i].x, v[i].y, h0, l0);
            split2t(v[i].z, v[i].w, h1, l1);
            uint32_t off = swz(r, m >> 1) + (m & 1) * 8;
            uint32_t* pH = reinterpret_cast<uint32_t*>(smem + SM_BH + off);
            uint32_t* pL = reinterpret_cast<uint32_t*>(smem + SM_BL + off);
            pH[0] = h0; pH[1] = h1;
            pL[0] = l0; pL[1] = l1;
        }
    }
    __syncthreads();

    // ---- warp tiling: 4 warps = 2 (M halves of 32) x 2 (N halves of 72) ----
    const int wm = wid & 1;
    const int wn = wid >> 1;
    const int g  = lane >> 2;
    const int tg = lane & 3;

    float acc[2][9][4] = {};   // [m-tile 16][n-tile 8][frag]

    // A ldmatrix lane row/chunk (row invariant to mt since mt*16 ≡ 0 mod 8)
    const int arow = wm * 32 + (lane & 15);
    const int achk = lane >> 4;               // 0/1 -> k chunks kk*2 + achk
    // B ldmatrix: x4 covers tiles (ntb, ntb+1); lanes>=16 take ntb+1
    const int brow0 = wn * 72 + (lane >> 4) * 8 + (lane & 7);
    const int bchk  = (lane >> 3) & 1;
    const int brow2 = wn * 72 + (lane & 7);   // for trailing x2 (tile 8)

    #pragma unroll
    for (int kk = 0; kk < 4; kk++) {
        uint32_t aH[2][4], aL[2][4], bH[9][2], bL[9][2];
        const uint32_t aoff = swz(arow, kk * 2 + achk);
        const uint32_t boff = swz(brow0, kk * 2 + bchk);
        const uint32_t boff2 = swz(brow2, kk * 2 + bchk);

        // pass 1: qh * Eh
        #pragma unroll
        for (int mt = 0; mt < 2; mt++)
            LDSM_X4(aH[mt][0], aH[mt][1], aH[mt][2], aH[mt][3],
                    sb + SM_AH + aoff + mt * 2048);
        #pragma unroll
        for (int p = 0; p < 4; p++)
            LDSM_X4(bH[2*p][0], bH[2*p][1], bH[2*p+1][0], bH[2*p+1][1],
                    sb + SM_BH + boff + p * 2048);
        LDSM_X2(bH[8][0], bH[8][1], sb + SM_BH + boff2 + 8192);
        #pragma unroll
        for (int mt = 0; mt < 2; mt++)
            #pragma unroll
            for (int nt = 0; nt < 9; nt++)
                MMA16816(acc[mt][nt], aH[mt], bH[nt]);

        // pass 2: qh * El   (reuse aH)
        #pragma unroll
        for (int p = 0; p < 4; p++)
            LDSM_X4(bL[2*p][0], bL[2*p][1], bL[2*p+1][0], bL[2*p+1][1],
                    sb + SM_BL + boff + p * 2048);
        LDSM_X2(bL[8][0], bL[8][1], sb + SM_BL + boff2 + 8192);
        #pragma unroll
        for (int mt = 0; mt < 2; mt++)
            #pragma unroll
            for (int nt = 0; nt < 9; nt++)
                MMA16816(acc[mt][nt], aH[mt], bL[nt]);

        // pass 3: ql * Eh   (reuse bH)
        #pragma unroll
        for (int mt = 0; mt < 2; mt++)
            LDSM_X4(aL[mt][0], aL[mt][1], aL[mt][2], aL[mt][3],
                    sb + SM_AL + aoff + mt * 2048);
        #pragma unroll
        for (int mt = 0; mt < 2; mt++)
            #pragma unroll
            for (int nt = 0; nt < 9; nt++)
                MMA16816(acc[mt][nt], aL[mt], bH[nt]);
    }
    __syncthreads();   // inputs dead; stage aliases them

    // ---- accum -> fp32 staging (window coords) ----
    float* st = reinterpret_cast<float*>(smem);
    #pragma unroll
    for (int mt = 0; mt < 2; mt++) {
        const int m0 = wm * 32 + mt * 16 + g;
        #pragma unroll
        for (int nt = 0; nt < 9; nt++) {
            const int n = wn * 72 + nt * 8 + 2 * tg;
            *reinterpret_cast<float2*>(&st[m0 * SP + n]) =
                make_float2(acc[mt][nt][0], acc[mt][nt][1]);
            *reinterpret_cast<float2*>(&st[(m0 + 8) * SP + n]) =
                make_float2(acc[mt][nt][2], acc[mt][nt][3]);
        }
    }
    __syncthreads();

    // ---- shifted read (column-strided, conflict-free) + coalesced writeout ----
    float* ob = out + ((size_t)b * T_DIM + t0) * S_DIM + 128 * sx;
    #pragma unroll
    for (int it = 0; it < 16; it++) {
        int idx = tid + 128 * it;
        int row = idx >> 5, m = idx & 31;
        int off = 15 - (row >> 2);
        const float* sr = &st[row * SP + off];
        float* orow = ob + row * S_DIM;
        #pragma unroll
        for (int k = 0; k < 4; k++)
            orow[m + 32 * k] = sr[m + 32 * k];
    }
}

extern "C" void kernel_launch(void* const* d_in, const int* in_sizes, int n_in,
                              void* d_out, int out_size)
{
    const float* q  = (const float*)d_in[0];
    const float* e1 = (const float*)d_in[1];
    const float* e2 = (const float*)d_in[2];
    float* out = (float*)d_out;

    cudaFuncSetAttribute(srel_mma,
                         cudaFuncAttributeMaxDynamicSharedMemorySize, SM_TOTAL);
    dim3 grid(T_DIM / BT, S_DIM / 128, 128);   // (16, 2, 128) = 4096 blocks
    srel_mma<<<grid, 128, SM_TOTAL>>>(q, e1, e2, out);
}